// round 1
// baseline (speedup 1.0000x reference)
#include <cuda_runtime.h>
#include <math.h>

// ---------------- problem constants ----------------
#define B_GRAPHS 2048
#define F_NODES  64
#define D_IN     32
#define HDIM     128
#define HEADS    4
#define NC       16
#define EPG      128
#define N_NODES  (B_GRAPHS * F_NODES)        // 131072
#define E_EDGES  (B_GRAPHS * EPG)            // 262144

// ---------------- scratch (device globals; no allocs) ----------------
__device__ float g_x[(size_t)N_NODES * HDIM];            // gated aligned features [N,128]
__device__ float g_h1[(size_t)N_NODES * HEADS * HDIM];   // [N,512]
__device__ float g_out1[(size_t)N_NODES * HEADS * HDIM]; // elu(gat1) [N,512]
__device__ float g_h2[(size_t)N_NODES * HDIM];           // [N,128]
__device__ float g_out2[(size_t)N_NODES * HDIM];         // gat2 out [N,128]

// ---------------- kernel 1: align + gate ----------------
// x[n,j] = (emb[n,:] @ W_align[:,j] + b_align[j]) * sigmoid(gate_logits[n%64])
__global__ __launch_bounds__(256) void align_gate_kernel(
    const float* __restrict__ emb, const float* __restrict__ W_align,
    const float* __restrict__ b_align, const float* __restrict__ gate_logits,
    float* __restrict__ x, float* __restrict__ gate_out)
{
    __shared__ float semb[8 * 32];
    __shared__ float sgate[64];
    int t = threadIdx.x;
    int j = t & 127, sub = t >> 7;

    float Wc[32];
#pragma unroll
    for (int k = 0; k < 32; k++) Wc[k] = W_align[k * 128 + j];
    float bj = b_align[j];

    if (t < 64) {
        float gv = 1.0f / (1.0f + expf(-gate_logits[t]));
        sgate[t] = gv;
        if (blockIdx.x == 0 && gate_out != nullptr) gate_out[t] = gv;
    }
    __syncthreads();

    int base = blockIdx.x * 256;   // 512 blocks * 256 nodes = 131072
    for (int i0 = 0; i0 < 256; i0 += 8) {
        int n0 = base + i0;
        semb[t] = emb[(size_t)n0 * 32 + t];
        __syncthreads();
        for (int s = sub; s < 8; s += 2) {
            int n = n0 + s;
            float acc = bj;
#pragma unroll
            for (int k = 0; k < 32; k++) acc = fmaf(semb[s * 32 + k], Wc[k], acc);
            x[(size_t)n * 128 + j] = acc * sgate[n & 63];
        }
        __syncthreads();
    }
}

// ---------------- kernel 2: SGEMM C[M,N] = A[M,K] @ B[K,N] ----------------
#define GBM 128
#define GBN 128
#define GBK 16
#define GTM 8
#define GTN 8

__global__ __launch_bounds__(256) void sgemm_kernel(
    int M, int N, int K,
    const float* __restrict__ A, const float* __restrict__ B, float* __restrict__ C)
{
    __shared__ __align__(16) float As[GBK][GBM];
    __shared__ __align__(16) float Bs[GBK][GBN];

    int tid = threadIdx.x;
    int cCol = blockIdx.x, cRow = blockIdx.y;

    const float* Ab = A + (size_t)cRow * GBM * K;
    const float* Bb = B + cCol * GBN;
    float* Cb = C + (size_t)cRow * GBM * N + cCol * GBN;

    int aRow = tid >> 2;             // 0..63
    int aCol = (tid & 3) * 4;        // 0,4,8,12
    int bRow = tid >> 5;             // 0..7
    int bCol = (tid & 31) * 4;       // 0..124

    int tCol = tid & 15;             // 16
    int tRow = tid >> 4;             // 16

    float acc[GTM][GTN];
#pragma unroll
    for (int i = 0; i < GTM; i++)
#pragma unroll
        for (int jj = 0; jj < GTN; jj++) acc[i][jj] = 0.f;

    float regM[GTM], regN[GTN];

    for (int k0 = 0; k0 < K; k0 += GBK) {
#pragma unroll
        for (int o = 0; o < GBM; o += 64) {
            float4 v = *reinterpret_cast<const float4*>(&Ab[(size_t)(aRow + o) * K + k0 + aCol]);
            As[aCol + 0][aRow + o] = v.x;
            As[aCol + 1][aRow + o] = v.y;
            As[aCol + 2][aRow + o] = v.z;
            As[aCol + 3][aRow + o] = v.w;
        }
#pragma unroll
        for (int o = 0; o < GBK; o += 8) {
            float4 v = *reinterpret_cast<const float4*>(&Bb[(size_t)(k0 + bRow + o) * N + bCol]);
            *reinterpret_cast<float4*>(&Bs[bRow + o][bCol]) = v;
        }
        __syncthreads();

#pragma unroll
        for (int k = 0; k < GBK; k++) {
#pragma unroll
            for (int i = 0; i < GTM; i += 4)
                *reinterpret_cast<float4*>(&regM[i]) =
                    *reinterpret_cast<const float4*>(&As[k][tRow * GTM + i]);
#pragma unroll
            for (int jj = 0; jj < GTN; jj += 4)
                *reinterpret_cast<float4*>(&regN[jj]) =
                    *reinterpret_cast<const float4*>(&Bs[k][tCol * GTN + jj]);
#pragma unroll
            for (int i = 0; i < GTM; i++)
#pragma unroll
                for (int jj = 0; jj < GTN; jj++)
                    acc[i][jj] = fmaf(regM[i], regN[jj], acc[i][jj]);
        }
        __syncthreads();
    }

#pragma unroll
    for (int i = 0; i < GTM; i++) {
#pragma unroll
        for (int jj = 0; jj < GTN; jj += 4) {
            float4 v;
            v.x = acc[i][jj]; v.y = acc[i][jj + 1]; v.z = acc[i][jj + 2]; v.w = acc[i][jj + 3];
            *reinterpret_cast<float4*>(&Cb[(size_t)(tRow * GTM + i) * N + tCol * GTN + jj]) = v;
        }
    }
}

// ---------------- kernel 3: per-(graph,head) GAT attention ----------------
__device__ __forceinline__ void atomicMaxFloatS(float* addr, float val) {
    int* ai = (int*)addr;
    int old = *ai;
    while (__int_as_float(old) < val) {
        int assumed = old;
        old = atomicCAS(ai, assumed, __float_as_int(val));
        if (old == assumed) break;
    }
}

__global__ __launch_bounds__(128) void gat_attn_kernel(
    const float* __restrict__ h, int ldh,
    const float* __restrict__ a_src, const float* __restrict__ a_dst,
    const float* __restrict__ bias,
    float* __restrict__ out, int ldo,
    const int* __restrict__ eidx, int apply_elu)
{
    __shared__ __align__(16) float sh[64 * 128];
    __shared__ float ssrc[64], sdst[64], smax[64], ssum[64];
    __shared__ float eprob[192];
    __shared__ int eS[192], eT[192];
    __shared__ int deg[64], startc[65], cursor[64];
    __shared__ int order[192];

    int b = blockIdx.x;
    int hoff = blockIdx.y * 128;
    int t = threadIdx.x;
    int node0 = b * 64;

    // load 64x128 head slice of h into smem (coalesced float4)
    for (int idx = t; idx < 64 * 32; idx += 128) {
        int row = idx >> 5, c = idx & 31;
        float4 v = *reinterpret_cast<const float4*>(&h[(size_t)(node0 + row) * ldh + hoff + c * 4]);
        *reinterpret_cast<float4*>(&sh[row * 128 + c * 4]) = v;
    }
    if (t < 64) { deg[t] = 0; cursor[t] = 0; smax[t] = -1e30f; ssum[t] = 0.f; }
    __syncthreads();

    // per-node attention scores: ssrc[i] = h[i,:]·a_src, sdst[i] = h[i,:]·a_dst
    {
        int w = t >> 5, l = t & 31;
        float asr[4], adr[4];
#pragma unroll
        for (int k = 0; k < 4; k++) {
            asr[k] = __ldg(&a_src[hoff + l * 4 + k]);
            adr[k] = __ldg(&a_dst[hoff + l * 4 + k]);
        }
        for (int i = w; i < 64; i += 4) {
            float4 hv = *reinterpret_cast<const float4*>(&sh[i * 128 + l * 4]);
            float s1 = hv.x * asr[0] + hv.y * asr[1] + hv.z * asr[2] + hv.w * asr[3];
            float s2 = hv.x * adr[0] + hv.y * adr[1] + hv.z * adr[2] + hv.w * adr[3];
#pragma unroll
            for (int off = 16; off > 0; off >>= 1) {
                s1 += __shfl_xor_sync(0xffffffffu, s1, off);
                s2 += __shfl_xor_sync(0xffffffffu, s2, off);
            }
            if (l == 0) { ssrc[i] = s1; sdst[i] = s2; }
        }
    }
    __syncthreads();

    // edge pass A: leaky-relu score, per-target max, degree count
    for (int e = t; e < 192; e += 128) {
        int s, tt;
        if (e < 128) {
            s  = eidx[b * 128 + e] - node0;
            tt = eidx[E_EDGES + b * 128 + e] - node0;
        } else {
            s = e - 128; tt = s;   // self-loop
        }
        eS[e] = s; eT[e] = tt;
        float sc = ssrc[s] + sdst[tt];
        sc = sc > 0.f ? sc : 0.2f * sc;
        eprob[e] = sc;
        atomicMaxFloatS(&smax[tt], sc);
        atomicAdd(&deg[tt], 1);
    }
    __syncthreads();
    if (t == 0) {
        int acc = 0;
        for (int i = 0; i < 64; i++) { startc[i] = acc; acc += deg[i]; }
        startc[64] = acc;
    }
    __syncthreads();

    // edge pass B: exp, per-target sum, CSR bucketing
    for (int e = t; e < 192; e += 128) {
        int tt = eT[e];
        float p = expf(eprob[e] - smax[tt]);
        eprob[e] = p;
        atomicAdd(&ssum[tt], p);
        int pos = atomicAdd(&cursor[tt], 1);
        order[startc[tt] + pos] = e;
    }
    __syncthreads();

    // aggregation: thread t owns feature d=t; normalize once per target
    {
        int d = t;
        float bd = __ldg(&bias[hoff + d]);
        for (int tt = 0; tt < 64; tt++) {
            float acc = 0.f;
            int s0 = startc[tt], s1 = startc[tt + 1];
            for (int k = s0; k < s1; k++) {
                int e = order[k];
                acc = fmaf(eprob[e], sh[eS[e] * 128 + d], acc);
            }
            float val = acc / (ssum[tt] + 1e-16f) + bd;
            if (apply_elu) val = val > 0.f ? val : (expf(val) - 1.f);
            out[(size_t)(node0 + tt) * ldo + hoff + d] = val;
        }
    }
}

// ---------------- kernel 4: global mean pool + classifier MLP ----------------
__global__ __launch_bounds__(128) void pool_cls_kernel(
    const float* __restrict__ out2,
    const float* __restrict__ Wc1, const float* __restrict__ bc1,
    const float* __restrict__ Wc2, const float* __restrict__ bc2,
    float* __restrict__ logits)
{
    int b = blockIdx.x, t = threadIdx.x;
    __shared__ float sg[128];
    __shared__ float shc[64];

    const float* base = out2 + (size_t)b * 64 * 128;
    float acc = 0.f;
#pragma unroll 8
    for (int i = 0; i < 64; i++) acc += base[i * 128 + t];
    sg[t] = acc * (1.0f / 64.0f);
    __syncthreads();

    if (t < 64) {
        float a = bc1[t];
#pragma unroll 8
        for (int d = 0; d < 128; d++) a = fmaf(sg[d], Wc1[d * 64 + t], a);
        shc[t] = a > 0.f ? a : 0.01f * a;
    }
    __syncthreads();

    if (t < 16) {
        float a = bc2[t];
#pragma unroll 8
        for (int j = 0; j < 64; j++) a = fmaf(shc[j], Wc2[j * 16 + t], a);
        logits[(size_t)b * 16 + t] = a;
    }
}

// ---------------- launch ----------------
extern "C" void kernel_launch(void* const* d_in, const int* in_sizes, int n_in,
                              void* d_out, int out_size)
{
    const float* emb         = (const float*)d_in[0];
    const int*   edge_index  = (const int*)d_in[1];
    // d_in[2] = batch_idx (structure known: repeat(arange(B), F)) — unused
    const float* W_align     = (const float*)d_in[3];
    const float* b_align     = (const float*)d_in[4];
    const float* gate_logits = (const float*)d_in[5];
    const float* W1          = (const float*)d_in[6];
    const float* a_src1      = (const float*)d_in[7];
    const float* a_dst1      = (const float*)d_in[8];
    const float* b1          = (const float*)d_in[9];
    const float* W2          = (const float*)d_in[10];
    const float* a_src2      = (const float*)d_in[11];
    const float* a_dst2      = (const float*)d_in[12];
    const float* b2          = (const float*)d_in[13];
    const float* Wc1         = (const float*)d_in[14];
    const float* bc1         = (const float*)d_in[15];
    const float* Wc2         = (const float*)d_in[16];
    const float* bc2         = (const float*)d_in[17];
    float* out = (float*)d_out;

    float *px, *ph1, *po1, *ph2, *po2;
    cudaGetSymbolAddress((void**)&px,  g_x);
    cudaGetSymbolAddress((void**)&ph1, g_h1);
    cudaGetSymbolAddress((void**)&po1, g_out1);
    cudaGetSymbolAddress((void**)&ph2, g_h2);
    cudaGetSymbolAddress((void**)&po2, g_out2);

    // gate output goes at the tail of the flattened (logits, gate) tuple
    float* gate_out = (out_size >= 64) ? (out + (out_size - 64)) : nullptr;

    // 1) align + gate  -> g_x [N,128]  (also writes gate to output tail)
    align_gate_kernel<<<512, 256>>>(emb, W_align, b_align, gate_logits, px, gate_out);

    // 2) h1 = x @ W1   [131072,128]@[128,512]
    sgemm_kernel<<<dim3(HEADS * HDIM / GBN, N_NODES / GBM), 256>>>(
        N_NODES, HEADS * HDIM, HDIM, px, W1, ph1);

    // 3) GAT layer 1 attention + elu -> g_out1 [N,512]
    gat_attn_kernel<<<dim3(B_GRAPHS, HEADS), 128>>>(
        ph1, HEADS * HDIM, a_src1, a_dst1, b1, po1, HEADS * HDIM, edge_index, 1);

    // 4) h2 = out1 @ W2  [131072,512]@[512,128]
    sgemm_kernel<<<dim3(HDIM / GBN, N_NODES / GBM), 256>>>(
        N_NODES, HDIM, HEADS * HDIM, po1, W2, ph2);

    // 5) GAT layer 2 attention (1 head, no elu) -> g_out2 [N,128]
    gat_attn_kernel<<<dim3(B_GRAPHS, 1), 128>>>(
        ph2, HDIM, a_src2, a_dst2, b2, po2, HDIM, edge_index, 0);

    // 6) mean pool + classifier -> logits [B,16]
    pool_cls_kernel<<<B_GRAPHS, 128>>>(po2, Wc1, bc1, Wc2, bc2, out);
}

// round 3
// speedup vs baseline: 1.7384x; 1.7384x over previous
#include <cuda_runtime.h>
#include <cuda_bf16.h>
#include <math.h>
#include <cstdint>

// ---------------- problem constants ----------------
#define B_GRAPHS 2048
#define F_NODES  64
#define D_IN     32
#define HDIM     128
#define HEADS    4
#define NC       16
#define EPG      128
#define N_NODES  (B_GRAPHS * F_NODES)        // 131072
#define E_EDGES  (B_GRAPHS * EPG)            // 262144

// ---------------- scratch (device globals; no allocs) ----------------
__device__ __nv_bfloat16 g_embh[(size_t)N_NODES * 32];
__device__ __nv_bfloat16 g_embl[(size_t)N_NODES * 32];
__device__ __nv_bfloat16 g_w1t_h[512 * 32];
__device__ __nv_bfloat16 g_w1t_l[512 * 32];
__device__ float         g_c1[512];
__device__ float         g_h1[(size_t)N_NODES * 512];
__device__ __nv_bfloat16 g_o1h[(size_t)N_NODES * 512];
__device__ __nv_bfloat16 g_o1l[(size_t)N_NODES * 512];
__device__ __nv_bfloat16 g_w2t_h[128 * 512];
__device__ __nv_bfloat16 g_w2t_l[128 * 512];
__device__ float         g_h2[(size_t)N_NODES * 128];
__device__ float         g_out2[(size_t)N_NODES * 128];

// ---------------- PTX helpers (sm_80+ compatible; no tcgen05) ----------------
__device__ __forceinline__ uint32_t smem_to_u32(const void* p) {
    uint32_t a;
    asm("{ .reg .u64 tmp; cvta.to.shared.u64 tmp, %1; cvt.u32.u64 %0, tmp; }" : "=r"(a) : "l"(p));
    return a;
}
__device__ __forceinline__ void cp16(uint32_t saddr, const void* g, bool valid) {
    int sz = valid ? 16 : 0;
    asm volatile("cp.async.cg.shared.global [%0], [%1], 16, %2;"
                 :: "r"(saddr), "l"(g), "r"(sz) : "memory");
}
#define CP_COMMIT() asm volatile("cp.async.commit_group;" ::: "memory")
#define CP_WAIT0()  asm volatile("cp.async.wait_group 0;" ::: "memory")
#define CP_WAIT1()  asm volatile("cp.async.wait_group 1;" ::: "memory")

#define LDSM_X4(r0, r1, r2, r3, addr) \
    asm volatile("ldmatrix.sync.aligned.m8n8.x4.shared.b16 {%0,%1,%2,%3}, [%4];" \
                 : "=r"(r0), "=r"(r1), "=r"(r2), "=r"(r3) : "r"(addr))

#define MMA16816(d, a, b0, b1) \
    asm volatile("mma.sync.aligned.m16n8k16.row.col.f32.bf16.bf16.f32 " \
                 "{%0,%1,%2,%3}, {%4,%5,%6,%7}, {%8,%9}, {%0,%1,%2,%3};" \
                 : "+f"((d)[0]), "+f"((d)[1]), "+f"((d)[2]), "+f"((d)[3]) \
                 : "r"((a)[0]), "r"((a)[1]), "r"((a)[2]), "r"((a)[3]), "r"(b0), "r"(b1))

// ---------------- prep kernels ----------------
__global__ __launch_bounds__(256) void prep_emb_split_kernel(
    const float4* __restrict__ e, __nv_bfloat162* __restrict__ eh, __nv_bfloat162* __restrict__ el)
{
    int i = blockIdx.x * 256 + threadIdx.x;     // 1,048,576 float4s
    float4 v = e[i];
    __nv_bfloat16 h0 = __float2bfloat16(v.x), h1 = __float2bfloat16(v.y);
    __nv_bfloat16 h2 = __float2bfloat16(v.z), h3 = __float2bfloat16(v.w);
    eh[2 * i]     = __nv_bfloat162(h0, h1);
    eh[2 * i + 1] = __nv_bfloat162(h2, h3);
    el[2 * i]     = __nv_bfloat162(__float2bfloat16(v.x - __bfloat162float(h0)),
                                   __float2bfloat16(v.y - __bfloat162float(h1)));
    el[2 * i + 1] = __nv_bfloat162(__float2bfloat16(v.z - __bfloat162float(h2)),
                                   __float2bfloat16(v.w - __bfloat162float(h3)));
}

// W1t[n][k] = (Wa @ W1)[k][n], split hi/lo
__global__ __launch_bounds__(256) void prep_w1t_kernel(
    const float* __restrict__ Wa, const float* __restrict__ W1,
    __nv_bfloat16* __restrict__ th, __nv_bfloat16* __restrict__ tl)
{
    int idx = blockIdx.x * 256 + threadIdx.x;   // 16384
    int k = idx >> 9, n = idx & 511;
    float acc = 0.f;
#pragma unroll 8
    for (int m = 0; m < 128; m++) acc = fmaf(Wa[k * 128 + m], W1[m * 512 + n], acc);
    __nv_bfloat16 h = __float2bfloat16(acc);
    th[n * 32 + k] = h;
    tl[n * 32 + k] = __float2bfloat16(acc - __bfloat162float(h));
}

// W2t[n][k] = W2[k][n], split hi/lo
__global__ __launch_bounds__(256) void prep_w2t_kernel(
    const float* __restrict__ W2, __nv_bfloat16* __restrict__ th, __nv_bfloat16* __restrict__ tl)
{
    int idx = blockIdx.x * 256 + threadIdx.x;   // 65536
    int n = idx >> 9, k = idx & 511;
    float v = W2[k * 128 + n];
    __nv_bfloat16 h = __float2bfloat16(v);
    th[n * 512 + k] = h;
    tl[n * 512 + k] = __float2bfloat16(v - __bfloat162float(h));
}

// c1[n] = b_align @ W1 ; gate tail output
__global__ __launch_bounds__(576) void prep_misc_kernel(
    const float* __restrict__ b_align, const float* __restrict__ W1,
    const float* __restrict__ gl, float* __restrict__ c1, float* __restrict__ gate_out)
{
    int t = threadIdx.x;
    if (t < 512) {
        float acc = 0.f;
#pragma unroll 8
        for (int m = 0; m < 128; m++) acc = fmaf(b_align[m], W1[m * 512 + t], acc);
        c1[t] = acc;
    } else if (t < 576 && gate_out != nullptr) {
        int f = t - 512;
        gate_out[f] = 1.0f / (1.0f + expf(-gl[f]));
    }
}

// ---------------- mma.sync bf16x3 GEMM ----------------
// C[m0:+128, n0:+128] = Ahl[M,K] @ Bhl[N,K]^T (3-pass hi/lo), fp32 accumulate.
// MODE 0: C = D.   MODE 1: C = sigmoid(gl[row%64]) * (D + c1[col]).
// smem: 2 buffers x {Ah, Al, Bh, Bl}[128 rows][64 bf16 + 8 pad] (stride 144 B)
#define ROWB   144
#define AOFF   (128 * ROWB)          // 18432 B per array
#define BUFB   (4 * AOFF)            // 73728 B per buffer
#define GEMM_SMEM_TOTAL (2 * BUFB)   // 147456 B

template <int MODE>
__global__ __launch_bounds__(256, 1) void gemm_mma_kernel(
    const __nv_bfloat16* __restrict__ Ah, const __nv_bfloat16* __restrict__ Al,
    const __nv_bfloat16* __restrict__ Bh, const __nv_bfloat16* __restrict__ Bl,
    float* __restrict__ C, int Kdim, int Nld,
    const float* __restrict__ c1, const float* __restrict__ gl)
{
    extern __shared__ char smem[];
    uint32_t sb = smem_to_u32(smem);
    int t = threadIdx.x, lane = t & 31, w = t >> 5;
    int wm = w >> 2, wn = w & 3;                 // warp tile: rows wm*64, cols wn*32
    int n0 = blockIdx.x * 128, m0 = blockIdx.y * 128;

    float acc[4][4][4];
#pragma unroll
    for (int i = 0; i < 4; i++)
#pragma unroll
        for (int j = 0; j < 4; j++)
#pragma unroll
            for (int r = 0; r < 4; r++) acc[i][j][r] = 0.f;

    int NKC = (Kdim + 63) >> 6;

    // cp.async mapping: k8 = t&7 (16B piece), rowgrp = t>>3 (+j*32)
    int k8 = t & 7, rg = t >> 3;
    const __nv_bfloat16* srcs[4] = { Ah, Al, Bh, Bl };
    int rbase[4] = { m0, m0, n0, n0 };

    auto load_chunk = [&](int c) {
        int kc = c << 6;
        uint32_t sbuf = sb + (uint32_t)(c & 1) * BUFB;
        bool v = (kc + k8 * 8) < Kdim;
#pragma unroll
        for (int arr = 0; arr < 4; arr++) {
            const __nv_bfloat16* P = srcs[arr];
#pragma unroll
            for (int j = 0; j < 4; j++) {
                int row = rg + j * 32;
                cp16(sbuf + arr * AOFF + row * ROWB + k8 * 16,
                     P + (size_t)(rbase[arr] + row) * Kdim + kc + k8 * 8, v);
            }
        }
    };

    // per-lane ldmatrix row offsets (lane&15 row, lane>>4 selects k-half)
    uint32_t aoff = (uint32_t)((wm * 64 + (lane & 15)) * ROWB + (lane >> 4) * 16);
    uint32_t boff = (uint32_t)((wn * 32 + (lane & 15)) * ROWB + (lane >> 4) * 16);

    load_chunk(0); CP_COMMIT();

    for (int c = 0; c < NKC; c++) {
        if (c + 1 < NKC) { load_chunk(c + 1); CP_COMMIT(); CP_WAIT1(); }
        else             { CP_WAIT0(); }
        __syncthreads();

        uint32_t sbuf = sb + (uint32_t)(c & 1) * BUFB;
        uint32_t aH = sbuf + aoff, aL = sbuf + AOFF + aoff;
        uint32_t bH = sbuf + 2 * AOFF + boff, bL = sbuf + 3 * AOFF + boff;
        int kkmax = min(4, (Kdim - (c << 6)) >> 4);

        for (int kk = 0; kk < kkmax; kk++) {
            uint32_t ko = kk * 32;
            uint32_t ah[4][4], al[4][4], bh[2][4], bl[2][4];
#pragma unroll
            for (int mt = 0; mt < 4; mt++) {
                LDSM_X4(ah[mt][0], ah[mt][1], ah[mt][2], ah[mt][3], aH + mt * (16 * ROWB) + ko);
                LDSM_X4(al[mt][0], al[mt][1], al[mt][2], al[mt][3], aL + mt * (16 * ROWB) + ko);
            }
#pragma unroll
            for (int s = 0; s < 2; s++) {
                LDSM_X4(bh[s][0], bh[s][1], bh[s][2], bh[s][3], bH + s * (16 * ROWB) + ko);
                LDSM_X4(bl[s][0], bl[s][1], bl[s][2], bl[s][3], bL + s * (16 * ROWB) + ko);
            }
#pragma unroll
            for (int mt = 0; mt < 4; mt++) {
#pragma unroll
                for (int nt = 0; nt < 4; nt++) {
                    int s = nt >> 1, o = nt & 1;   // reg pair: (o, o+2)
                    MMA16816(acc[mt][nt], ah[mt], bh[s][o], bh[s][o + 2]);
                    MMA16816(acc[mt][nt], ah[mt], bl[s][o], bl[s][o + 2]);
                    MMA16816(acc[mt][nt], al[mt], bh[s][o], bh[s][o + 2]);
                }
            }
        }
        __syncthreads();
    }

    // epilogue: thread holds C[row + {0,8}][col + {0,1}] per (mt,nt)
    int gr = lane >> 2, gc = (lane & 3) * 2;
#pragma unroll
    for (int mt = 0; mt < 4; mt++) {
        int row = m0 + wm * 64 + mt * 16 + gr;
        float g0 = 1.f, g1 = 1.f;
        if (MODE == 1) {
            g0 = 1.0f / (1.0f + expf(-__ldg(&gl[row & 63])));
            g1 = 1.0f / (1.0f + expf(-__ldg(&gl[(row + 8) & 63])));
        }
#pragma unroll
        for (int nt = 0; nt < 4; nt++) {
            int col = n0 + wn * 32 + nt * 8 + gc;
            float c0 = 0.f, c1v = 0.f;
            if (MODE == 1) { c0 = __ldg(&c1[col]); c1v = __ldg(&c1[col + 1]); }
            float2 v0, v1;
            if (MODE == 1) {
                v0.x = g0 * (acc[mt][nt][0] + c0); v0.y = g0 * (acc[mt][nt][1] + c1v);
                v1.x = g1 * (acc[mt][nt][2] + c0); v1.y = g1 * (acc[mt][nt][3] + c1v);
            } else {
                v0.x = acc[mt][nt][0]; v0.y = acc[mt][nt][1];
                v1.x = acc[mt][nt][2]; v1.y = acc[mt][nt][3];
            }
            *(float2*)(C + (size_t)row * Nld + col) = v0;
            *(float2*)(C + (size_t)(row + 8) * Nld + col) = v1;
        }
    }
}

// ---------------- GAT attention (per graph, per head) ----------------
__device__ __forceinline__ void atomicMaxFloatS(float* addr, float val) {
    int* ai = (int*)addr;
    int old = *ai;
    while (__int_as_float(old) < val) {
        int assumed = old;
        old = atomicCAS(ai, assumed, __float_as_int(val));
        if (old == assumed) break;
    }
}

template <int SPLIT, int ELU>
__global__ __launch_bounds__(128) void gat_attn_kernel(
    const float* __restrict__ h, int ldh,
    const float* __restrict__ a_src, const float* __restrict__ a_dst,
    const float* __restrict__ bias,
    float* __restrict__ out, __nv_bfloat16* __restrict__ outh, __nv_bfloat16* __restrict__ outl,
    int ldo, const int* __restrict__ eidx)
{
    __shared__ __align__(16) float sh[64 * 128];
    __shared__ float ssrc[64], sdst[64], smax[64], ssum[64];
    __shared__ float eprob[192];
    __shared__ int eS[192], eT[192];
    __shared__ int deg[64], startc[65], cursor[64];
    __shared__ int order[192];

    int b = blockIdx.x;
    int hoff = blockIdx.y * 128;
    int t = threadIdx.x;
    int node0 = b * 64;

    for (int idx = t; idx < 64 * 32; idx += 128) {
        int row = idx >> 5, c = idx & 31;
        float4 v = *reinterpret_cast<const float4*>(&h[(size_t)(node0 + row) * ldh + hoff + c * 4]);
        *reinterpret_cast<float4*>(&sh[row * 128 + c * 4]) = v;
    }
    if (t < 64) { deg[t] = 0; cursor[t] = 0; smax[t] = -1e30f; ssum[t] = 0.f; }
    __syncthreads();

    {
        int w = t >> 5, l = t & 31;
        float asr[4], adr[4];
#pragma unroll
        for (int k = 0; k < 4; k++) {
            asr[k] = __ldg(&a_src[hoff + l * 4 + k]);
            adr[k] = __ldg(&a_dst[hoff + l * 4 + k]);
        }
        for (int i = w; i < 64; i += 4) {
            float4 hv = *reinterpret_cast<const float4*>(&sh[i * 128 + l * 4]);
            float s1 = hv.x * asr[0] + hv.y * asr[1] + hv.z * asr[2] + hv.w * asr[3];
            float s2 = hv.x * adr[0] + hv.y * adr[1] + hv.z * adr[2] + hv.w * adr[3];
#pragma unroll
            for (int off = 16; off > 0; off >>= 1) {
                s1 += __shfl_xor_sync(0xffffffffu, s1, off);
                s2 += __shfl_xor_sync(0xffffffffu, s2, off);
            }
            if (l == 0) { ssrc[i] = s1; sdst[i] = s2; }
        }
    }
    __syncthreads();

    for (int e = t; e < 192; e += 128) {
        int s, tt;
        if (e < 128) {
            s  = eidx[b * 128 + e] - node0;
            tt = eidx[E_EDGES + b * 128 + e] - node0;
        } else {
            s = e - 128; tt = s;
        }
        eS[e] = s; eT[e] = tt;
        float sc = ssrc[s] + sdst[tt];
        sc = sc > 0.f ? sc : 0.2f * sc;
        eprob[e] = sc;
        atomicMaxFloatS(&smax[tt], sc);
        atomicAdd(&deg[tt], 1);
    }
    __syncthreads();
    if (t == 0) {
        int acc = 0;
        for (int i = 0; i < 64; i++) { startc[i] = acc; acc += deg[i]; }
        startc[64] = acc;
    }
    __syncthreads();

    for (int e = t; e < 192; e += 128) {
        int tt = eT[e];
        float p = expf(eprob[e] - smax[tt]);
        eprob[e] = p;
        atomicAdd(&ssum[tt], p);
        int pos = atomicAdd(&cursor[tt], 1);
        order[startc[tt] + pos] = e;
    }
    __syncthreads();

    {
        int d = t;
        float bd = __ldg(&bias[hoff + d]);
        for (int tt = 0; tt < 64; tt++) {
            float acc = 0.f;
            int s0 = startc[tt], s1 = startc[tt + 1];
            for (int k = s0; k < s1; k++) {
                int e = order[k];
                acc = fmaf(eprob[e], sh[eS[e] * 128 + d], acc);
            }
            float val = acc / (ssum[tt] + 1e-16f) + bd;
            if (ELU) val = val > 0.f ? val : (expf(val) - 1.f);
            size_t o = (size_t)(node0 + tt) * ldo + hoff + d;
            if (SPLIT) {
                __nv_bfloat16 hi = __float2bfloat16(val);
                outh[o] = hi;
                outl[o] = __float2bfloat16(val - __bfloat162float(hi));
            } else {
                out[o] = val;
            }
        }
    }
}

// ---------------- pool + classifier ----------------
__global__ __launch_bounds__(128) void pool_cls_kernel(
    const float* __restrict__ out2,
    const float* __restrict__ Wc1, const float* __restrict__ bc1,
    const float* __restrict__ Wc2, const float* __restrict__ bc2,
    float* __restrict__ logits)
{
    int b = blockIdx.x, t = threadIdx.x;
    __shared__ float sg[128];
    __shared__ float shc[64];

    const float* base = out2 + (size_t)b * 64 * 128;
    float acc = 0.f;
#pragma unroll 8
    for (int i = 0; i < 64; i++) acc += base[i * 128 + t];
    sg[t] = acc * (1.0f / 64.0f);
    __syncthreads();

    if (t < 64) {
        float a = bc1[t];
#pragma unroll 8
        for (int d = 0; d < 128; d++) a = fmaf(sg[d], Wc1[d * 64 + t], a);
        shc[t] = a > 0.f ? a : 0.01f * a;
    }
    __syncthreads();

    if (t < 16) {
        float a = bc2[t];
#pragma unroll 8
        for (int j = 0; j < 64; j++) a = fmaf(shc[j], Wc2[j * 16 + t], a);
        logits[(size_t)b * 16 + t] = a;
    }
}

// ---------------- launch ----------------
extern "C" void kernel_launch(void* const* d_in, const int* in_sizes, int n_in,
                              void* d_out, int out_size)
{
    const float* emb         = (const float*)d_in[0];
    const int*   edge_index  = (const int*)d_in[1];
    const float* W_align     = (const float*)d_in[3];
    const float* b_align     = (const float*)d_in[4];
    const float* gate_logits = (const float*)d_in[5];
    const float* W1          = (const float*)d_in[6];
    const float* a_src1      = (const float*)d_in[7];
    const float* a_dst1      = (const float*)d_in[8];
    const float* b1          = (const float*)d_in[9];
    const float* W2          = (const float*)d_in[10];
    const float* a_src2      = (const float*)d_in[11];
    const float* a_dst2      = (const float*)d_in[12];
    const float* b2          = (const float*)d_in[13];
    const float* Wc1         = (const float*)d_in[14];
    const float* bc1         = (const float*)d_in[15];
    const float* Wc2         = (const float*)d_in[16];
    const float* bc2         = (const float*)d_in[17];
    float* out = (float*)d_out;

    __nv_bfloat16 *embh, *embl, *w1th, *w1tl, *o1h, *o1l, *w2th, *w2tl;
    float *c1, *h1, *h2, *o2;
    cudaGetSymbolAddress((void**)&embh, g_embh);
    cudaGetSymbolAddress((void**)&embl, g_embl);
    cudaGetSymbolAddress((void**)&w1th, g_w1t_h);
    cudaGetSymbolAddress((void**)&w1tl, g_w1t_l);
    cudaGetSymbolAddress((void**)&c1,   g_c1);
    cudaGetSymbolAddress((void**)&h1,   g_h1);
    cudaGetSymbolAddress((void**)&o1h,  g_o1h);
    cudaGetSymbolAddress((void**)&o1l,  g_o1l);
    cudaGetSymbolAddress((void**)&w2th, g_w2t_h);
    cudaGetSymbolAddress((void**)&w2tl, g_w2t_l);
    cudaGetSymbolAddress((void**)&h2,   g_h2);
    cudaGetSymbolAddress((void**)&o2,   g_out2);

    cudaFuncSetAttribute(gemm_mma_kernel<0>, cudaFuncAttributeMaxDynamicSharedMemorySize, GEMM_SMEM_TOTAL);
    cudaFuncSetAttribute(gemm_mma_kernel<1>, cudaFuncAttributeMaxDynamicSharedMemorySize, GEMM_SMEM_TOTAL);

    float* gate_out = (out_size >= 64) ? (out + (out_size - 64)) : nullptr;

    // prep: bf16 hi/lo splits of emb, fused/transposed weights, c1, gate
    prep_emb_split_kernel<<<4096, 256>>>((const float4*)emb, (__nv_bfloat162*)embh, (__nv_bfloat162*)embl);
    prep_w1t_kernel<<<64, 256>>>(W_align, W1, w1th, w1tl);
    prep_w2t_kernel<<<256, 256>>>(W2, w2th, w2tl);
    prep_misc_kernel<<<1, 576>>>(b_align, W1, gate_logits, c1, gate_out);

    // h1 = diag(sigmoid(gl)) * (emb @ (Wa@W1) + c1)   [131072,512], K=32
    gemm_mma_kernel<1><<<dim3(4, 1024), 256, GEMM_SMEM_TOTAL>>>(
        embh, embl, w1th, w1tl, h1, 32, 512, c1, gate_logits);

    // GAT layer 1 (+b1, elu) -> bf16 hi/lo split out1
    gat_attn_kernel<1, 1><<<dim3(B_GRAPHS, HEADS), 128>>>(
        h1, 512, a_src1, a_dst1, b1, nullptr, o1h, o1l, 512, edge_index);

    // h2 = out1 @ W2   [131072,128], K=512
    gemm_mma_kernel<0><<<dim3(1, 1024), 256, GEMM_SMEM_TOTAL>>>(
        o1h, o1l, w2th, w2tl, h2, 512, 128, nullptr, nullptr);

    // GAT layer 2 (+b2, no elu) -> fp32 out2
    gat_attn_kernel<0, 0><<<dim3(B_GRAPHS, 1), 128>>>(
        h2, 128, a_src2, a_dst2, b2, o2, nullptr, nullptr, 128, edge_index);

    // pool + classifier
    pool_cls_kernel<<<B_GRAPHS, 128>>>(o2, Wc1, bc1, Wc2, bc2, out);
}